// round 2
// baseline (speedup 1.0000x reference)
#include <cuda_runtime.h>

#define NN   50000
#define DD   128
#define HH   2
#define CC   128
#define HCC  256
#define EE   800000
#define EP   (EE + NN)     // edges + self loops = 850000
#define OUTC 2
#define NEG  0.2f

// ---------------- scratch (device globals; no allocation allowed) ----------
__device__ float g_bufA[NN * HCC];     // 51.2 MB
__device__ float g_bufB[NN * HCC];     // 51.2 MB
__device__ float g_as[NN * HH];
__device__ float g_ad[NN * HH];
__device__ float g_m[NN * HH];
__device__ float g_den[NN * HH];
__device__ float g_lg[EP * HH];        // per-edge logits, then exp() values
__device__ int   g_src[EP];
__device__ int   g_dst[EP];
__device__ int   g_is64;

// ---------------- helpers ---------------------------------------------------
__device__ __forceinline__ void atomicMaxF(float* addr, float v) {
    // order-independent float max via int/uint atomics
    if (v >= 0.f) atomicMax((int*)addr, __float_as_int(v));
    else          atomicMin((unsigned int*)addr, __float_as_uint(v));
}

// ---------------- edge dtype probe + conversion -----------------------------
__global__ void detect_kernel(const int* __restrict__ ei_raw) {
    // int64 little-endian with values < 2^31 => odd 32-bit words are all 0.
    // int32 random node ids in [0,50000) => overwhelmingly nonzero odd words.
    int z = 0;
#pragma unroll
    for (int i = 0; i < 16; i++) z += (ei_raw[2 * i + 1] == 0);
    g_is64 = (z == 16);
}

__global__ void convert_kernel(const int* __restrict__ ei_raw) {
    int e = blockIdx.x * 256 + threadIdx.x;
    if (e >= EP) return;
    if (e >= EE) {                 // self loops
        g_src[e] = e - EE;
        g_dst[e] = e - EE;
        return;
    }
    if (g_is64) {                  // int64: take low word of each element
        g_src[e] = ei_raw[2 * e];
        g_dst[e] = ei_raw[2 * (EE + e)];
    } else {                       // int32
        g_src[e] = ei_raw[e];
        g_dst[e] = ei_raw[EE + e];
    }
}

// ---------------- GEMM: out[N,256] = A[N,K] @ W[K,256] ---------------------
template <int K>
__global__ void gemm_kernel(const float* __restrict__ A,
                            const float* __restrict__ W,
                            float* __restrict__ out, int nrows) {
    __shared__ float xs[8][K];
    const int tid  = threadIdx.x;            // 128 threads
    const int row0 = blockIdx.x * 8;

    for (int i = tid; i < 8 * K; i += 128) {
        int r = i / K, c = i % K;
        int gr = row0 + r;
        xs[r][c] = (gr < nrows) ? A[gr * K + c] : 0.f;
    }
    __syncthreads();

    float acc0[8], acc1[8];
#pragma unroll
    for (int r = 0; r < 8; r++) { acc0[r] = 0.f; acc1[r] = 0.f; }

    const int c0 = tid, c1 = tid + 128;
    for (int k = 0; k < K; k++) {
        float w0 = W[k * HCC + c0];
        float w1 = W[k * HCC + c1];
#pragma unroll
        for (int r = 0; r < 8; r++) {
            float xv = xs[r][k];
            acc0[r] = fmaf(xv, w0, acc0[r]);
            acc1[r] = fmaf(xv, w1, acc1[r]);
        }
    }
#pragma unroll
    for (int r = 0; r < 8; r++) {
        int gr = row0 + r;
        if (gr < nrows) {
            out[gr * HCC + c0] = acc0[r];
            out[gr * HCC + c1] = acc1[r];
        }
    }
}

// ---------------- per-(node,head) attention dots ----------------------------
__global__ void attvec_kernel(const float* __restrict__ h,
                              const float* __restrict__ att_s,
                              const float* __restrict__ att_d) {
    int task = blockIdx.x * 4 + (threadIdx.x >> 5);   // one warp per (n,h)
    if (task >= NN * HH) return;
    int lane = threadIdx.x & 31;
    int n = task >> 1, hh = task & 1;

    float4 hv = ((const float4*)(h + n * HCC + hh * CC))[lane];
    float4 sv = ((const float4*)(att_s + hh * CC))[lane];
    float4 dv = ((const float4*)(att_d + hh * CC))[lane];
    float s = hv.x * sv.x + hv.y * sv.y + hv.z * sv.z + hv.w * sv.w;
    float d = hv.x * dv.x + hv.y * dv.y + hv.z * dv.z + hv.w * dv.w;
#pragma unroll
    for (int o = 16; o; o >>= 1) {
        s += __shfl_down_sync(0xffffffffu, s, o);
        d += __shfl_down_sync(0xffffffffu, d, o);
    }
    if (lane == 0) { g_as[task] = s; g_ad[task] = d; }
}

// ---------------- init: zero accum buffer, m=-inf, den=0 --------------------
__global__ void init_kernel(float* __restrict__ outbuf) {
    int i = blockIdx.x * 256 + threadIdx.x;
    if (i < NN * HCC) outbuf[i] = 0.f;
    if (i < NN * HH) { g_m[i] = __int_as_float(0xff800000); g_den[i] = 0.f; }
}

// ---------------- edge pass 1: logits + segment max -------------------------
__global__ void edge_logit_max() {
    int e = blockIdx.x * 256 + threadIdx.x;
    if (e >= EP) return;
    int src = g_src[e], dst = g_dst[e];
#pragma unroll
    for (int hh = 0; hh < HH; hh++) {
        float l = g_as[src * HH + hh] + g_ad[dst * HH + hh];
        l = (l > 0.f) ? l : NEG * l;
        g_lg[e * HH + hh] = l;
        atomicMaxF(&g_m[dst * HH + hh], l);
    }
}

// ---------------- edge pass 2: exp + segment sum ----------------------------
__global__ void edge_exp_sum() {
    int e = blockIdx.x * 256 + threadIdx.x;
    if (e >= EP) return;
    int dst = g_dst[e];
#pragma unroll
    for (int hh = 0; hh < HH; hh++) {
        float ev = expf(g_lg[e * HH + hh] - g_m[dst * HH + hh]);
        g_lg[e * HH + hh] = ev;
        atomicAdd(&g_den[dst * HH + hh], ev);
    }
}

// ---------------- edge pass 3: weighted scatter -----------------------------
__global__ void edge_scatter(const float* __restrict__ h,
                             float* __restrict__ out) {
    int t = threadIdx.x;                      // 256 threads = all HC channels
    int hh = t >> 7;
    int e0 = blockIdx.x * 4;
#pragma unroll
    for (int i = 0; i < 4; i++) {
        int e = e0 + i;
        if (e >= EP) return;
        int src = g_src[e], dst = g_dst[e];
        float alpha = g_lg[e * HH + hh] / (g_den[dst * HH + hh] + 1e-16f);
        atomicAdd(&out[dst * HCC + t], h[src * HCC + t] * alpha);
    }
}

// ---------------- bias (+ optional tanh) ------------------------------------
__global__ void bias_act(float* __restrict__ buf, const float* __restrict__ b,
                         int do_tanh) {
    int i = blockIdx.x * 256 + threadIdx.x;
    if (i >= NN * HCC) return;
    float v = buf[i] + b[i & 255];
    buf[i] = do_tanh ? tanhf(v) : v;
}

// ---------------- final linear 256->2 + softmax -----------------------------
__global__ void final_kernel(const float* __restrict__ h,
                             const float* __restrict__ Wl,
                             const float* __restrict__ bl,
                             float* __restrict__ out) {
    int n = blockIdx.x * 8 + (threadIdx.x >> 5);  // warp per node
    if (n >= NN) return;
    int lane = threadIdx.x & 31;
    const float4* hp = (const float4*)(h + n * HCC);   // 64 float4
    float s0 = 0.f, s1 = 0.f;
#pragma unroll
    for (int i = 0; i < 2; i++) {
        int q = lane + i * 32;                 // float4 index, c = 4q
        float4 hv = hp[q];
        float4 wa = ((const float4*)Wl)[q * 2];      // rows c, c+1
        float4 wb = ((const float4*)Wl)[q * 2 + 1];  // rows c+2, c+3
        s0 += hv.x * wa.x + hv.y * wa.z + hv.z * wb.x + hv.w * wb.z;
        s1 += hv.x * wa.y + hv.y * wa.w + hv.z * wb.y + hv.w * wb.w;
    }
#pragma unroll
    for (int o = 16; o; o >>= 1) {
        s0 += __shfl_down_sync(0xffffffffu, s0, o);
        s1 += __shfl_down_sync(0xffffffffu, s1, o);
    }
    if (lane == 0) {
        float o0 = s0 + bl[0], o1 = s1 + bl[1];
        float mx = fmaxf(o0, o1);
        float e0 = expf(o0 - mx), e1 = expf(o1 - mx);
        float inv = 1.f / (e0 + e1);
        out[n * OUTC + 0] = e0 * inv;
        out[n * OUTC + 1] = e1 * inv;
    }
}

// ---------------- launch ----------------------------------------------------
extern "C" void kernel_launch(void* const* d_in, const int* in_sizes, int n_in,
                              void* d_out, int out_size) {
    const float* x    = (const float*)d_in[0];
    const int*   ei   = (const int*)d_in[1];     // int32 OR int64(low/high words)
    const float* W0   = (const float*)d_in[2];
    const float* as0  = (const float*)d_in[3];
    const float* ad0  = (const float*)d_in[4];
    const float* b0   = (const float*)d_in[5];
    const float* W1   = (const float*)d_in[6];
    const float* as1  = (const float*)d_in[7];
    const float* ad1  = (const float*)d_in[8];
    const float* b1   = (const float*)d_in[9];
    const float* Wl   = (const float*)d_in[10];
    const float* bl   = (const float*)d_in[11];
    float*       out  = (float*)d_out;

    float *bufA, *bufB;
    cudaGetSymbolAddress((void**)&bufA, g_bufA);
    cudaGetSymbolAddress((void**)&bufB, g_bufB);

    const int gElem  = (NN * HCC + 255) / 256;   // 50000
    const int gEdge  = (EP + 255) / 256;         // 3321
    const int gScat  = (EP + 3) / 4;             // 212500
    const int gAtt   = (NN * HH + 3) / 4;        // 25000
    const int gGemm  = (NN + 7) / 8;             // 6250

    // ---- edge index normalization (dtype-agnostic) ----
    detect_kernel<<<1, 1>>>(ei);
    convert_kernel<<<gEdge, 256>>>(ei);

    // ---- layer 0: x @ W0 -> bufA; edge aggregation -> bufB; tanh ----
    gemm_kernel<DD><<<gGemm, 128>>>(x, W0, bufA, NN);
    attvec_kernel<<<gAtt, 128>>>(bufA, as0, ad0);
    init_kernel<<<gElem, 256>>>(bufB);
    edge_logit_max<<<gEdge, 256>>>();
    edge_exp_sum<<<gEdge, 256>>>();
    edge_scatter<<<gScat, 256>>>(bufA, bufB);
    bias_act<<<gElem, 256>>>(bufB, b0, 1);

    // ---- layer 1: bufB @ W1 -> bufA; edge aggregation -> bufB ----
    gemm_kernel<HCC><<<gGemm, 128>>>(bufB, W1, bufA, NN);
    attvec_kernel<<<gAtt, 128>>>(bufA, as1, ad1);
    init_kernel<<<gElem, 256>>>(bufB);
    edge_logit_max<<<gEdge, 256>>>();
    edge_exp_sum<<<gEdge, 256>>>();
    edge_scatter<<<gScat, 256>>>(bufA, bufB);
    bias_act<<<gElem, 256>>>(bufB, b1, 0);

    // ---- head: bufB @ Wl + bl, softmax ----
    final_kernel<<<gGemm, 256>>>(bufB, Wl, bl, out);
}

// round 8
// speedup vs baseline: 2.5353x; 2.5353x over previous
#include <cuda_runtime.h>

#define NN   50000
#define DD   128
#define HH   2
#define CC   128
#define HCC  256
#define EE   800000
#define EP   (EE + NN)     // edges + self loops = 850000
#define OUTC 2
#define NEG  0.2f
#define NINF (-1e30f)

// ---------------- scratch (device globals; no allocation allowed) ----------
__device__ float g_bufA[NN * HCC];     // 51.2 MB
__device__ float g_bufB[NN * HCC];     // 51.2 MB
__device__ float g_as[NN * HH];
__device__ float g_ad[NN * HH];
__device__ int   g_srcL[EP];
__device__ int   g_dstL[EP];
__device__ int   g_csr[EP];            // src ids sorted by dst
__device__ int   g_deg[NN];
__device__ int   g_fill[NN];
__device__ int   g_rowptr[NN + 1];
__device__ int   g_is64;

// ---------------- f32x2 helpers ---------------------------------------------
__device__ __forceinline__ unsigned long long splat2(float v) {
    unsigned long long r;
    asm("mov.b64 %0, {%1, %1};" : "=l"(r) : "f"(v));
    return r;
}
__device__ __forceinline__ void fma2(unsigned long long& d,
                                     unsigned long long a,
                                     unsigned long long b) {
    asm("fma.rn.f32x2 %0, %1, %2, %0;" : "+l"(d) : "l"(a), "l"(b));
}
__device__ __forceinline__ float2 unpack2(unsigned long long u) {
    float2 f;
    asm("mov.b64 {%0, %1}, %2;" : "=f"(f.x), "=f"(f.y) : "l"(u));
    return f;
}

// ---------------- edge dtype probe + conversion -----------------------------
__global__ void detect_kernel(const int* __restrict__ ei_raw) {
    int z = 0;
#pragma unroll
    for (int i = 0; i < 16; i++) z += (ei_raw[2 * i + 1] == 0);
    g_is64 = (z == 16);
}

__global__ void convert_kernel(const int* __restrict__ ei_raw) {
    int e = blockIdx.x * 256 + threadIdx.x;
    if (e >= EP) return;
    if (e >= EE) { g_srcL[e] = e - EE; g_dstL[e] = e - EE; return; }
    if (g_is64) { g_srcL[e] = ei_raw[2 * e]; g_dstL[e] = ei_raw[2 * (EE + e)]; }
    else        { g_srcL[e] = ei_raw[e];     g_dstL[e] = ei_raw[EE + e]; }
}

// ---------------- CSR build --------------------------------------------------
__global__ void zero_cnt_kernel() {
    int i = blockIdx.x * 256 + threadIdx.x;
    if (i < NN) { g_deg[i] = 0; g_fill[i] = 0; }
}
__global__ void hist_kernel() {
    int e = blockIdx.x * 256 + threadIdx.x;
    if (e < EP) atomicAdd(&g_deg[g_dstL[e]], 1);
}
__global__ void scan_kernel() {          // single block, 1024 threads
    __shared__ int ssum[1024];
    const int t = threadIdx.x;
    const int CH = (NN + 1023) / 1024;   // 49
    int base = t * CH;
    int s = 0;
    for (int i = 0; i < CH; i++) {
        int idx = base + i;
        if (idx < NN) s += g_deg[idx];
    }
    ssum[t] = s;
    __syncthreads();
    for (int off = 1; off < 1024; off <<= 1) {
        int v = (t >= off) ? ssum[t - off] : 0;
        __syncthreads();
        ssum[t] += v;
        __syncthreads();
    }
    int run = ssum[t] - s;               // exclusive prefix
    for (int i = 0; i < CH; i++) {
        int idx = base + i;
        if (idx < NN) { g_rowptr[idx] = run; run += g_deg[idx]; }
    }
    if (t == 1023) g_rowptr[NN] = run;
}
__global__ void fill_kernel() {
    int e = blockIdx.x * 256 + threadIdx.x;
    if (e >= EP) return;
    int dst = g_dstL[e];
    int pos = g_rowptr[dst] + atomicAdd(&g_fill[dst], 1);
    g_csr[pos] = g_srcL[e];
}

// ---------------- GEMM: out[N,256] = A[N,K] @ W[K,256], f32x2 ---------------
// 64x256 block tile, BK=32, 256 threads, 8x8 micro-tile per thread.
template <int K>
__global__ void __launch_bounds__(256)
gemm_kernel(const float* __restrict__ A, const float* __restrict__ W,
            float* __restrict__ out) {
    __shared__ unsigned long long As2[32][66];   // pre-splatted A, [k][row]
    __shared__ float Bs[32][256];

    const int tid = threadIdx.x;
    const int tx  = tid & 31;
    const int ty  = tid >> 5;                    // warp id 0..7
    const int row0 = blockIdx.x * 64;

    unsigned long long acc[8][4];
#pragma unroll
    for (int r = 0; r < 8; r++)
#pragma unroll
        for (int j = 0; j < 4; j++) acc[r][j] = 0ull;

    const int lrow = tid & 63;                   // A-loader row
    const int lkq  = tid >> 6;                   // 0..3

    for (int kk = 0; kk < K; kk += 32) {
        // load A tile (transposed + splatted)
#pragma unroll
        for (int j = 0; j < 2; j++) {
            float4 v = make_float4(0.f, 0.f, 0.f, 0.f);
            int gr = row0 + lrow;
            if (gr < NN)
                v = *(const float4*)&A[gr * K + kk + lkq * 8 + j * 4];
            int kb = lkq * 8 + j * 4;
            As2[kb + 0][lrow] = splat2(v.x);
            As2[kb + 1][lrow] = splat2(v.y);
            As2[kb + 2][lrow] = splat2(v.z);
            As2[kb + 3][lrow] = splat2(v.w);
        }
        // load B tile
#pragma unroll
        for (int i = 0; i < 8; i++) {
            int f  = tid + i * 256;              // float4 index
            int k  = f >> 6;
            int cq = f & 63;
            *(float4*)&Bs[k][cq * 4] = *(const float4*)&W[(kk + k) * HCC + cq * 4];
        }
        __syncthreads();

#pragma unroll 8
        for (int k = 0; k < 32; k++) {
            ulonglong2 a01 = *(const ulonglong2*)&As2[k][ty * 8 + 0];
            ulonglong2 a23 = *(const ulonglong2*)&As2[k][ty * 8 + 2];
            ulonglong2 a45 = *(const ulonglong2*)&As2[k][ty * 8 + 4];
            ulonglong2 a67 = *(const ulonglong2*)&As2[k][ty * 8 + 6];
            ulonglong2 b0  = *(const ulonglong2*)&Bs[k][tx * 4];
            ulonglong2 b1  = *(const ulonglong2*)&Bs[k][128 + tx * 4];
            unsigned long long av[8] = {a01.x, a01.y, a23.x, a23.y,
                                        a45.x, a45.y, a67.x, a67.y};
#pragma unroll
            for (int r = 0; r < 8; r++) {
                fma2(acc[r][0], av[r], b0.x);
                fma2(acc[r][1], av[r], b0.y);
                fma2(acc[r][2], av[r], b1.x);
                fma2(acc[r][3], av[r], b1.y);
            }
        }
        __syncthreads();
    }

#pragma unroll
    for (int r = 0; r < 8; r++) {
        int gr = row0 + ty * 8 + r;
        if (gr >= NN) continue;
        float2 p0 = unpack2(acc[r][0]), p1 = unpack2(acc[r][1]);
        float2 p2 = unpack2(acc[r][2]), p3 = unpack2(acc[r][3]);
        *(float4*)&out[gr * HCC + tx * 4]       = make_float4(p0.x, p0.y, p1.x, p1.y);
        *(float4*)&out[gr * HCC + 128 + tx * 4] = make_float4(p2.x, p2.y, p3.x, p3.y);
    }
}

// ---------------- per-(node,head) attention dots ----------------------------
__global__ void attvec_kernel(const float* __restrict__ h,
                              const float* __restrict__ att_s,
                              const float* __restrict__ att_d) {
    int task = blockIdx.x * 4 + (threadIdx.x >> 5);   // one warp per (n,h)
    if (task >= NN * HH) return;
    int lane = threadIdx.x & 31;
    int n = task >> 1, hh = task & 1;

    float4 hv = ((const float4*)(h + n * HCC + hh * CC))[lane];
    float4 sv = ((const float4*)(att_s + hh * CC))[lane];
    float4 dv = ((const float4*)(att_d + hh * CC))[lane];
    float s = hv.x * sv.x + hv.y * sv.y + hv.z * sv.z + hv.w * sv.w;
    float d = hv.x * dv.x + hv.y * dv.y + hv.z * dv.z + hv.w * dv.w;
#pragma unroll
    for (int o = 16; o; o >>= 1) {
        s += __shfl_down_sync(0xffffffffu, s, o);
        d += __shfl_down_sync(0xffffffffu, d, o);
    }
    if (lane == 0) { g_as[task] = s; g_ad[task] = d; }
}

// ---------------- fused GAT aggregation (softmax + gather + epilogue) -------
// One warp per dst node. mode 0: out = tanh(agg + bias) -> outbuf
// mode 1: v = agg + bias; out = softmax(v @ Wl + bl)    -> outfinal
__device__ __forceinline__ float lrelu(float v) { return v > 0.f ? v : NEG * v; }

__global__ void gat_agg(const float* __restrict__ h,
                        const float* __restrict__ bias,
                        const float* __restrict__ Wl,
                        const float* __restrict__ bl,
                        float* __restrict__ outbuf,
                        float* __restrict__ outfinal, int mode) {
    int d = blockIdx.x * 8 + (threadIdx.x >> 5);
    if (d >= NN) return;
    int lane = threadIdx.x & 31;

    int start = g_rowptr[d], end = g_rowptr[d + 1];
    float2 adv = ((const float2*)g_ad)[d];
    const float2* as2 = (const float2*)g_as;

    // phase A1: segment max per head
    float m0 = NINF, m1 = NINF;
    for (int e = start + lane; e < end; e += 32) {
        float2 a = as2[g_csr[e]];
        m0 = fmaxf(m0, lrelu(a.x + adv.x));
        m1 = fmaxf(m1, lrelu(a.y + adv.y));
    }
#pragma unroll
    for (int o = 16; o; o >>= 1) {
        m0 = fmaxf(m0, __shfl_xor_sync(0xffffffffu, m0, o));
        m1 = fmaxf(m1, __shfl_xor_sync(0xffffffffu, m1, o));
    }
    // phase A2: denominators
    float den0 = 0.f, den1 = 0.f;
    for (int e = start + lane; e < end; e += 32) {
        float2 a = as2[g_csr[e]];
        den0 += __expf(lrelu(a.x + adv.x) - m0);
        den1 += __expf(lrelu(a.y + adv.y) - m1);
    }
#pragma unroll
    for (int o = 16; o; o >>= 1) {
        den0 += __shfl_xor_sync(0xffffffffu, den0, o);
        den1 += __shfl_xor_sync(0xffffffffu, den1, o);
    }
    float r0 = 1.f / (den0 + 1e-16f);
    float r1 = 1.f / (den1 + 1e-16f);

    // phase B: weighted gather. lane covers channels lane*4..+3 (head0)
    // and 128+lane*4..+3 (head1).
    float4 acc0 = make_float4(0.f, 0.f, 0.f, 0.f);
    float4 acc1 = make_float4(0.f, 0.f, 0.f, 0.f);
    const float4* h4 = (const float4*)h;
    for (int e = start; e < end; e++) {
        int s = g_csr[e];
        float2 a = as2[s];
        float w0 = __expf(lrelu(a.x + adv.x) - m0) * r0;
        float w1 = __expf(lrelu(a.y + adv.y) - m1) * r1;
        float4 v0 = h4[s * 64 + lane];
        float4 v1 = h4[s * 64 + 32 + lane];
        acc0.x = fmaf(v0.x, w0, acc0.x); acc0.y = fmaf(v0.y, w0, acc0.y);
        acc0.z = fmaf(v0.z, w0, acc0.z); acc0.w = fmaf(v0.w, w0, acc0.w);
        acc1.x = fmaf(v1.x, w1, acc1.x); acc1.y = fmaf(v1.y, w1, acc1.y);
        acc1.z = fmaf(v1.z, w1, acc1.z); acc1.w = fmaf(v1.w, w1, acc1.w);
    }

    float4 bb0 = ((const float4*)bias)[lane];
    float4 bb1 = ((const float4*)bias)[32 + lane];
    acc0.x += bb0.x; acc0.y += bb0.y; acc0.z += bb0.z; acc0.w += bb0.w;
    acc1.x += bb1.x; acc1.y += bb1.y; acc1.z += bb1.z; acc1.w += bb1.w;

    if (mode == 0) {
        acc0.x = tanhf(acc0.x); acc0.y = tanhf(acc0.y);
        acc0.z = tanhf(acc0.z); acc0.w = tanhf(acc0.w);
        acc1.x = tanhf(acc1.x); acc1.y = tanhf(acc1.y);
        acc1.z = tanhf(acc1.z); acc1.w = tanhf(acc1.w);
        float4* o4 = (float4*)outbuf;
        o4[d * 64 + lane]      = acc0;
        o4[d * 64 + 32 + lane] = acc1;
    } else {
        // final linear 256->2 + softmax, fused
        const float4* wl4 = (const float4*)Wl;   // [c][2] flat
        float4 wa0 = wl4[lane * 2],      wb0 = wl4[lane * 2 + 1];
        float4 wa1 = wl4[64 + lane * 2], wb1 = wl4[64 + lane * 2 + 1];
        float s0 = acc0.x * wa0.x + acc0.y * wa0.z + acc0.z * wb0.x + acc0.w * wb0.z
                 + acc1.x * wa1.x + acc1.y * wa1.z + acc1.z * wb1.x + acc1.w * wb1.z;
        float s1 = acc0.x * wa0.y + acc0.y * wa0.w + acc0.z * wb0.y + acc0.w * wb0.w
                 + acc1.x * wa1.y + acc1.y * wa1.w + acc1.z * wb1.y + acc1.w * wb1.w;
#pragma unroll
        for (int o = 16; o; o >>= 1) {
            s0 += __shfl_xor_sync(0xffffffffu, s0, o);
            s1 += __shfl_xor_sync(0xffffffffu, s1, o);
        }
        if (lane == 0) {
            float o0 = s0 + bl[0], o1 = s1 + bl[1];
            float mx = fmaxf(o0, o1);
            float e0 = __expf(o0 - mx), e1 = __expf(o1 - mx);
            float inv = 1.f / (e0 + e1);
            outfinal[d * OUTC + 0] = e0 * inv;
            outfinal[d * OUTC + 1] = e1 * inv;
        }
    }
}

// ---------------- launch ----------------------------------------------------
extern "C" void kernel_launch(void* const* d_in, const int* in_sizes, int n_in,
                              void* d_out, int out_size) {
    const float* x    = (const float*)d_in[0];
    const int*   ei   = (const int*)d_in[1];
    const float* W0   = (const float*)d_in[2];
    const float* as0  = (const float*)d_in[3];
    const float* ad0  = (const float*)d_in[4];
    const float* b0   = (const float*)d_in[5];
    const float* W1   = (const float*)d_in[6];
    const float* as1  = (const float*)d_in[7];
    const float* ad1  = (const float*)d_in[8];
    const float* b1   = (const float*)d_in[9];
    const float* Wl   = (const float*)d_in[10];
    const float* bl   = (const float*)d_in[11];
    float*       out  = (float*)d_out;

    float *bufA, *bufB;
    cudaGetSymbolAddress((void**)&bufA, g_bufA);
    cudaGetSymbolAddress((void**)&bufB, g_bufB);

    const int gEdge = (EP + 255) / 256;          // 3321
    const int gNode = (NN + 255) / 256;          // 196
    const int gAtt  = (NN * HH + 3) / 4;         // 25000
    const int gGemm = (NN + 63) / 64;            // 782
    const int gAgg  = (NN + 7) / 8;              // 6250

    // ---- edge normalization + CSR build (reused by both layers) ----
    detect_kernel<<<1, 1>>>(ei);
    convert_kernel<<<gEdge, 256>>>(ei);
    zero_cnt_kernel<<<gNode, 256>>>();
    hist_kernel<<<gEdge, 256>>>();
    scan_kernel<<<1, 1024>>>();
    fill_kernel<<<gEdge, 256>>>();

    // ---- layer 0 ----
    gemm_kernel<DD><<<gGemm, 256>>>(x, W0, bufA);
    attvec_kernel<<<gAtt, 128>>>(bufA, as0, ad0);
    gat_agg<<<gAgg, 256>>>(bufA, b0, nullptr, nullptr, bufB, nullptr, 0);

    // ---- layer 1 (+ fused final linear & softmax) ----
    gemm_kernel<HCC><<<gGemm, 256>>>(bufB, W1, bufA);
    attvec_kernel<<<gAtt, 128>>>(bufA, as1, ad1);
    gat_agg<<<gAgg, 256>>>(bufA, b1, Wl, bl, nullptr, out, 1);
}

// round 16
// speedup vs baseline: 2.6458x; 1.0435x over previous
#include <cuda_runtime.h>

#define NN   50000
#define DD   128
#define HH   2
#define CC   128
#define HCC  256
#define EE   800000
#define EP   (EE + NN)     // edges + self loops = 850000
#define OUTC 2
#define NEG  0.2f
#define NINF (-1e30f)

// ---------------- scratch (device globals; no allocation allowed) ----------
__device__ float g_bufA[NN * HCC];     // 51.2 MB
__device__ float g_bufB[NN * HCC];     // 51.2 MB
__device__ float g_as[NN * HH];
__device__ float g_ad[NN * HH];
__device__ int   g_srcL[EP];
__device__ int   g_dstL[EP];
__device__ int   g_csr[EP];            // src ids sorted by dst
__device__ int   g_deg[NN];
__device__ int   g_fill[NN];
__device__ int   g_rowptr[NN + 1];

// ---------------- f32x2 helpers ---------------------------------------------
__device__ __forceinline__ unsigned long long splat2(float v) {
    unsigned long long r;
    asm("mov.b64 %0, {%1, %1};" : "=l"(r) : "f"(v));
    return r;
}
__device__ __forceinline__ void fma2(unsigned long long& d,
                                     unsigned long long a,
                                     unsigned long long b) {
    asm("fma.rn.f32x2 %0, %1, %2, %0;" : "+l"(d) : "l"(a), "l"(b));
}
__device__ __forceinline__ float2 unpack2(unsigned long long u) {
    float2 f;
    asm("mov.b64 {%0, %1}, %2;" : "=f"(f.x), "=f"(f.y) : "l"(u));
    return f;
}

// ---------------- CSR build --------------------------------------------------
__global__ void zero_cnt_kernel() {
    int i = blockIdx.x * 256 + threadIdx.x;
    if (i < NN) { g_deg[i] = 0; g_fill[i] = 0; }
}

// convert (dtype-agnostic) + histogram in one pass; per-block dtype probe.
__global__ void convert_hist_kernel(const int* __restrict__ ei_raw) {
    __shared__ int sh_is64;
    if (threadIdx.x == 0) {
        int z = 0;
#pragma unroll
        for (int i = 0; i < 16; i++) z += (ei_raw[2 * i + 1] == 0);
        sh_is64 = (z == 16);
    }
    __syncthreads();
    int e = blockIdx.x * 256 + threadIdx.x;
    if (e >= EP) return;
    int src, dst;
    if (e >= EE)          { src = e - EE;        dst = e - EE; }
    else if (sh_is64)     { src = ei_raw[2 * e]; dst = ei_raw[2 * (EE + e)]; }
    else                  { src = ei_raw[e];     dst = ei_raw[EE + e]; }
    g_srcL[e] = src;
    g_dstL[e] = dst;
    atomicAdd(&g_deg[dst], 1);
}

__global__ void scan_kernel() {          // single block, 1024 threads
    __shared__ int ssum[1024];
    const int t = threadIdx.x;
    const int CH = (NN + 1023) / 1024;   // 49
    int base = t * CH;
    int s = 0;
    for (int i = 0; i < CH; i++) {
        int idx = base + i;
        if (idx < NN) s += g_deg[idx];
    }
    ssum[t] = s;
    __syncthreads();
    for (int off = 1; off < 1024; off <<= 1) {
        int v = (t >= off) ? ssum[t - off] : 0;
        __syncthreads();
        ssum[t] += v;
        __syncthreads();
    }
    int run = ssum[t] - s;               // exclusive prefix
    for (int i = 0; i < CH; i++) {
        int idx = base + i;
        if (idx < NN) { g_rowptr[idx] = run; run += g_deg[idx]; }
    }
    if (t == 1023) g_rowptr[NN] = run;
}
__global__ void fill_kernel() {
    int e = blockIdx.x * 256 + threadIdx.x;
    if (e >= EP) return;
    int dst = g_dstL[e];
    int pos = g_rowptr[dst] + atomicAdd(&g_fill[dst], 1);
    g_csr[pos] = g_srcL[e];
}

// ---------------- GEMM + fused attention dots -------------------------------
// out[N,256] = A[N,K] @ W[K,256]; also g_as/g_ad dots vs att_s/att_d.
// 64x256 block tile, BK=32, 256 threads, 8x8 micro-tile per thread, f32x2.
template <int K>
__global__ void __launch_bounds__(256)
gemm_kernel(const float* __restrict__ A, const float* __restrict__ W,
            const float* __restrict__ att_s, const float* __restrict__ att_d,
            float* __restrict__ out) {
    __shared__ unsigned long long As2[32][66];   // pre-splatted A, [k][row]
    __shared__ float Bs[32][256];
    __shared__ float Satt[HCC], Datt[HCC];

    const int tid = threadIdx.x;
    const int tx  = tid & 31;
    const int ty  = tid >> 5;                    // warp id 0..7
    const int row0 = blockIdx.x * 64;

    if (tid < HCC) { Satt[tid] = att_s[tid]; Datt[tid] = att_d[tid]; }

    unsigned long long acc[8][4];
#pragma unroll
    for (int r = 0; r < 8; r++)
#pragma unroll
        for (int j = 0; j < 4; j++) acc[r][j] = 0ull;

    const int lrow = tid & 63;                   // A-loader row
    const int lkq  = tid >> 6;                   // 0..3

    for (int kk = 0; kk < K; kk += 32) {
        // load A tile (transposed + splatted)
#pragma unroll
        for (int j = 0; j < 2; j++) {
            float4 v = make_float4(0.f, 0.f, 0.f, 0.f);
            int gr = row0 + lrow;
            if (gr < NN)
                v = *(const float4*)&A[gr * K + kk + lkq * 8 + j * 4];
            int kb = lkq * 8 + j * 4;
            As2[kb + 0][lrow] = splat2(v.x);
            As2[kb + 1][lrow] = splat2(v.y);
            As2[kb + 2][lrow] = splat2(v.z);
            As2[kb + 3][lrow] = splat2(v.w);
        }
        // load B tile
#pragma unroll
        for (int i = 0; i < 8; i++) {
            int f  = tid + i * 256;              // float4 index
            int k  = f >> 6;
            int cq = f & 63;
            *(float4*)&Bs[k][cq * 4] = *(const float4*)&W[(kk + k) * HCC + cq * 4];
        }
        __syncthreads();

#pragma unroll 8
        for (int k = 0; k < 32; k++) {
            ulonglong2 a01 = *(const ulonglong2*)&As2[k][ty * 8 + 0];
            ulonglong2 a23 = *(const ulonglong2*)&As2[k][ty * 8 + 2];
            ulonglong2 a45 = *(const ulonglong2*)&As2[k][ty * 8 + 4];
            ulonglong2 a67 = *(const ulonglong2*)&As2[k][ty * 8 + 6];
            ulonglong2 b0  = *(const ulonglong2*)&Bs[k][tx * 4];
            ulonglong2 b1  = *(const ulonglong2*)&Bs[k][128 + tx * 4];
            unsigned long long av[8] = {a01.x, a01.y, a23.x, a23.y,
                                        a45.x, a45.y, a67.x, a67.y};
#pragma unroll
            for (int r = 0; r < 8; r++) {
                fma2(acc[r][0], av[r], b0.x);
                fma2(acc[r][1], av[r], b0.y);
                fma2(acc[r][2], av[r], b1.x);
                fma2(acc[r][3], av[r], b1.y);
            }
        }
        __syncthreads();
    }

#pragma unroll
    for (int r = 0; r < 8; r++) {
        int gr = row0 + ty * 8 + r;
        if (gr >= NN) continue;                  // uniform per warp
        float2 p0 = unpack2(acc[r][0]), p1 = unpack2(acc[r][1]);
        float2 p2 = unpack2(acc[r][2]), p3 = unpack2(acc[r][3]);
        *(float4*)&out[gr * HCC + tx * 4]       = make_float4(p0.x, p0.y, p1.x, p1.y);
        *(float4*)&out[gr * HCC + 128 + tx * 4] = make_float4(p2.x, p2.y, p3.x, p3.y);

        // fused attention dots: lane tx covers c=4tx..4tx+3 (h0), 128+4tx.. (h1)
        int c0 = 4 * tx, c1 = 128 + 4 * tx;
        float s0 = p0.x * Satt[c0] + p0.y * Satt[c0 + 1]
                 + p1.x * Satt[c0 + 2] + p1.y * Satt[c0 + 3];
        float s1 = p2.x * Satt[c1] + p2.y * Satt[c1 + 1]
                 + p3.x * Satt[c1 + 2] + p3.y * Satt[c1 + 3];
        float d0 = p0.x * Datt[c0] + p0.y * Datt[c0 + 1]
                 + p1.x * Datt[c0 + 2] + p1.y * Datt[c0 + 3];
        float d1 = p2.x * Datt[c1] + p2.y * Datt[c1 + 1]
                 + p3.x * Datt[c1 + 2] + p3.y * Datt[c1 + 3];
#pragma unroll
        for (int o = 16; o; o >>= 1) {
            s0 += __shfl_xor_sync(0xffffffffu, s0, o);
            s1 += __shfl_xor_sync(0xffffffffu, s1, o);
            d0 += __shfl_xor_sync(0xffffffffu, d0, o);
            d1 += __shfl_xor_sync(0xffffffffu, d1, o);
        }
        if (tx == 0) {
            g_as[gr * 2 + 0] = s0; g_as[gr * 2 + 1] = s1;
            g_ad[gr * 2 + 0] = d0; g_ad[gr * 2 + 1] = d1;
        }
    }
}

// ---------------- fused GAT aggregation (softmax + gather + epilogue) -------
// One warp per dst node. mode 0: out = tanh(agg + bias) -> outbuf
// mode 1: v = agg + bias; out = softmax(v @ Wl + bl)    -> outfinal
__device__ __forceinline__ float lrelu(float v) { return v > 0.f ? v : NEG * v; }

__global__ void gat_agg(const float* __restrict__ h,
                        const float* __restrict__ bias,
                        const float* __restrict__ Wl,
                        const float* __restrict__ bl,
                        float* __restrict__ outbuf,
                        float* __restrict__ outfinal, int mode) {
    int d = blockIdx.x * 8 + (threadIdx.x >> 5);
    if (d >= NN) return;
    int lane = threadIdx.x & 31;

    int start = g_rowptr[d], end = g_rowptr[d + 1];
    float2 adv = ((const float2*)g_ad)[d];
    const float2* as2 = (const float2*)g_as;

    // phase A1: segment max per head
    float m0 = NINF, m1 = NINF;
    for (int e = start + lane; e < end; e += 32) {
        float2 a = as2[g_csr[e]];
        m0 = fmaxf(m0, lrelu(a.x + adv.x));
        m1 = fmaxf(m1, lrelu(a.y + adv.y));
    }
#pragma unroll
    for (int o = 16; o; o >>= 1) {
        m0 = fmaxf(m0, __shfl_xor_sync(0xffffffffu, m0, o));
        m1 = fmaxf(m1, __shfl_xor_sync(0xffffffffu, m1, o));
    }
    // phase A2: denominators
    float den0 = 0.f, den1 = 0.f;
    for (int e = start + lane; e < end; e += 32) {
        float2 a = as2[g_csr[e]];
        den0 += __expf(lrelu(a.x + adv.x) - m0);
        den1 += __expf(lrelu(a.y + adv.y) - m1);
    }
#pragma unroll
    for (int o = 16; o; o >>= 1) {
        den0 += __shfl_xor_sync(0xffffffffu, den0, o);
        den1 += __shfl_xor_sync(0xffffffffu, den1, o);
    }
    float r0 = 1.f / (den0 + 1e-16f);
    float r1 = 1.f / (den1 + 1e-16f);

    // phase B: weighted gather. Weights computed once per edge (lane-parallel
    // over a 32-edge chunk), then broadcast via shuffle — 32x fewer MUFU ops.
    float4 acc0 = make_float4(0.f, 0.f, 0.f, 0.f);
    float4 acc1 = make_float4(0.f, 0.f, 0.f, 0.f);
    const float4* h4 = (const float4*)h;
    for (int ebase = start; ebase < end; ebase += 32) {
        int nchunk = min(32, end - ebase);
        float w0v = 0.f, w1v = 0.f; int sv = 0;
        if (lane < nchunk) {
            sv = g_csr[ebase + lane];
            float2 a = as2[sv];
            w0v = __expf(lrelu(a.x + adv.x) - m0) * r0;
            w1v = __expf(lrelu(a.y + adv.y) - m1) * r1;
        }
        for (int j = 0; j < nchunk; j++) {
            int   s  = __shfl_sync(0xffffffffu, sv, j);
            float w0 = __shfl_sync(0xffffffffu, w0v, j);
            float w1 = __shfl_sync(0xffffffffu, w1v, j);
            float4 v0 = h4[s * 64 + lane];
            float4 v1 = h4[s * 64 + 32 + lane];
            acc0.x = fmaf(v0.x, w0, acc0.x); acc0.y = fmaf(v0.y, w0, acc0.y);
            acc0.z = fmaf(v0.z, w0, acc0.z); acc0.w = fmaf(v0.w, w0, acc0.w);
            acc1.x = fmaf(v1.x, w1, acc1.x); acc1.y = fmaf(v1.y, w1, acc1.y);
            acc1.z = fmaf(v1.z, w1, acc1.z); acc1.w = fmaf(v1.w, w1, acc1.w);
        }
    }

    float4 bb0 = ((const float4*)bias)[lane];
    float4 bb1 = ((const float4*)bias)[32 + lane];
    acc0.x += bb0.x; acc0.y += bb0.y; acc0.z += bb0.z; acc0.w += bb0.w;
    acc1.x += bb1.x; acc1.y += bb1.y; acc1.z += bb1.z; acc1.w += bb1.w;

    if (mode == 0) {
        acc0.x = tanhf(acc0.x); acc0.y = tanhf(acc0.y);
        acc0.z = tanhf(acc0.z); acc0.w = tanhf(acc0.w);
        acc1.x = tanhf(acc1.x); acc1.y = tanhf(acc1.y);
        acc1.z = tanhf(acc1.z); acc1.w = tanhf(acc1.w);
        float4* o4 = (float4*)outbuf;
        o4[d * 64 + lane]      = acc0;
        o4[d * 64 + 32 + lane] = acc1;
    } else {
        // final linear 256->2 + softmax, fused
        const float4* wl4 = (const float4*)Wl;   // [c][2] flat
        float4 wa0 = wl4[lane * 2],      wb0 = wl4[lane * 2 + 1];
        float4 wa1 = wl4[64 + lane * 2], wb1 = wl4[64 + lane * 2 + 1];
        float s0 = acc0.x * wa0.x + acc0.y * wa0.z + acc0.z * wb0.x + acc0.w * wb0.z
                 + acc1.x * wa1.x + acc1.y * wa1.z + acc1.z * wb1.x + acc1.w * wb1.z;
        float s1 = acc0.x * wa0.y + acc0.y * wa0.w + acc0.z * wb0.y + acc0.w * wb0.w
                 + acc1.x * wa1.y + acc1.y * wa1.w + acc1.z * wb1.y + acc1.w * wb1.w;
#pragma unroll
        for (int o = 16; o; o >>= 1) {
            s0 += __shfl_xor_sync(0xffffffffu, s0, o);
            s1 += __shfl_xor_sync(0xffffffffu, s1, o);
        }
        if (lane == 0) {
            float o0 = s0 + bl[0], o1 = s1 + bl[1];
            float mx = fmaxf(o0, o1);
            float e0 = __expf(o0 - mx), e1 = __expf(o1 - mx);
            float inv = 1.f / (e0 + e1);
            outfinal[d * OUTC + 0] = e0 * inv;
            outfinal[d * OUTC + 1] = e1 * inv;
        }
    }
}

// ---------------- launch ----------------------------------------------------
extern "C" void kernel_launch(void* const* d_in, const int* in_sizes, int n_in,
                              void* d_out, int out_size) {
    const float* x    = (const float*)d_in[0];
    const int*   ei   = (const int*)d_in[1];
    const float* W0   = (const float*)d_in[2];
    const float* as0  = (const float*)d_in[3];
    const float* ad0  = (const float*)d_in[4];
    const float* b0   = (const float*)d_in[5];
    const float* W1   = (const float*)d_in[6];
    const float* as1  = (const float*)d_in[7];
    const float* ad1  = (const float*)d_in[8];
    const float* b1   = (const float*)d_in[9];
    const float* Wl   = (const float*)d_in[10];
    const float* bl   = (const float*)d_in[11];
    float*       out  = (float*)d_out;

    float *bufA, *bufB;
    cudaGetSymbolAddress((void**)&bufA, g_bufA);
    cudaGetSymbolAddress((void**)&bufB, g_bufB);

    const int gEdge = (EP + 255) / 256;          // 3321
    const int gNode = (NN + 255) / 256;          // 196
    const int gGemm = (NN + 63) / 64;            // 782
    const int gAgg  = (NN + 7) / 8;              // 6250

    // ---- CSR build (reused by both layers) ----
    zero_cnt_kernel<<<gNode, 256>>>();
    convert_hist_kernel<<<gEdge, 256>>>(ei);
    scan_kernel<<<1, 1024>>>();
    fill_kernel<<<gEdge, 256>>>();

    // ---- layer 0 ----
    gemm_kernel<DD><<<gGemm, 256>>>(x, W0, as0, ad0, bufA);
    gat_agg<<<gAgg, 256>>>(bufA, b0, nullptr, nullptr, bufB, nullptr, 0);

    // ---- layer 1 (+ fused final linear & softmax) ----
    gemm_kernel<HCC><<<gGemm, 256>>>(bufB, W1, as1, ad1, bufA);
    gat_agg<<<gAgg, 256>>>(bufA, b1, Wl, bl, nullptr, out, 1);
}